// round 6
// baseline (speedup 1.0000x reference)
#include <cuda_runtime.h>
#include <cstdint>

#define N_NODES 100000
#define D 128

// ---------------- scratch (float4-typed => 16B aligned) ----------------
__device__ float4 g_g4[(size_t)N_NODES * (D / 4)];    // g = dinv * (x @ W^T)
__device__ float4 g_agg4[(size_t)N_NODES * (D / 4)];  // accumulator, init = g (self loop)
__device__ float  g_Wt[D * D];                        // W transposed
__device__ int    g_deg[N_NODES];                     // edge-count per dst
__device__ int    g_is64;                             // 1 if edge_index is int64, 0 if int32

// ---------------- dtype detect ----------------
// If data is int64 (values < 2^31), the int32 view is [lo,0,lo,0,...].
// If data is int32, odd words are random indices (virtually never all zero).
__global__ void detect_kernel(const int* __restrict__ ei32, int n_pairs) {
    __shared__ int nz;
    if (threadIdx.x == 0) nz = 0;
    __syncthreads();
    int local = 0;
    for (int i = threadIdx.x; i < n_pairs; i += blockDim.x)
        if (ei32[2 * i + 1] != 0) local = 1;
    if (local) atomicOr(&nz, 1);
    __syncthreads();
    if (threadIdx.x == 0) g_is64 = (nz == 0) ? 1 : 0;
}

__global__ void init_deg_kernel(int n) {
    int i = blockIdx.x * blockDim.x + threadIdx.x;
    if (i < n) g_deg[i] = 0;
}

__global__ void deg_kernel(const void* __restrict__ ei, int E) {
    int i = blockIdx.x * blockDim.x + threadIdx.x;
    if (i >= E) return;
    int d;
    if (g_is64) d = (int)((const long long*)ei)[(size_t)E + i];
    else        d = ((const int*)ei)[(size_t)E + i];
    if ((unsigned)d < (unsigned)N_NODES) atomicAdd(&g_deg[d], 1);
}

__global__ void transpose_W_kernel(const float* __restrict__ W) {
    int i = blockIdx.x * blockDim.x + threadIdx.x;
    if (i < D * D) {
        int n = i >> 7;
        int k = i & 127;
        g_Wt[k * D + n] = W[n * D + k];
    }
}

// Tiled SGEMM: h = x @ W^T, fused with dinv scaling; writes g and agg(=g).
#define BM 128
#define KT 32
__global__ __launch_bounds__(256) void gemm_scale_kernel(
    const float* __restrict__ x, int N)
{
    __shared__ float xs[BM][KT + 1];
    __shared__ float ws[KT][D];

    const int tid = threadIdx.x;
    const int tx = tid & 15;
    const int ty = tid >> 4;
    const int m0 = ty * 8;
    const int n0 = tx * 8;
    const int rowBase = blockIdx.x * BM;

    float c[8][8];
#pragma unroll
    for (int i = 0; i < 8; i++)
#pragma unroll
        for (int j = 0; j < 8; j++) c[i][j] = 0.0f;

    for (int kt = 0; kt < D; kt += KT) {
#pragma unroll
        for (int it = 0; it < 4; it++) {
            int i = tid + it * 256;
            int m = i >> 3;
            int kq = i & 7;
            float4 v = make_float4(0.f, 0.f, 0.f, 0.f);
            int row = rowBase + m;
            if (row < N)
                v = *(const float4*)(x + (size_t)row * D + kt + kq * 4);
            xs[m][kq * 4 + 0] = v.x;
            xs[m][kq * 4 + 1] = v.y;
            xs[m][kq * 4 + 2] = v.z;
            xs[m][kq * 4 + 3] = v.w;
        }
#pragma unroll
        for (int it = 0; it < 4; it++) {
            int i = tid + it * 256;
            int k = i >> 5;
            int nq = i & 31;
            float4 v = *(const float4*)(g_Wt + (size_t)(kt + k) * D + nq * 4);
            ws[k][nq * 4 + 0] = v.x;
            ws[k][nq * 4 + 1] = v.y;
            ws[k][nq * 4 + 2] = v.z;
            ws[k][nq * 4 + 3] = v.w;
        }
        __syncthreads();

#pragma unroll 8
        for (int k = 0; k < KT; k++) {
            float a[8], b[8];
#pragma unroll
            for (int i = 0; i < 8; i++) a[i] = xs[m0 + i][k];
#pragma unroll
            for (int j = 0; j < 8; j++) b[j] = ws[k][n0 + j];
#pragma unroll
            for (int i = 0; i < 8; i++)
#pragma unroll
                for (int j = 0; j < 8; j++)
                    c[i][j] = fmaf(a[i], b[j], c[i][j]);
        }
        __syncthreads();
    }

    // epilogue: g = dinv * h ; agg = g (self-loop contribution)
#pragma unroll
    for (int i = 0; i < 8; i++) {
        int row = rowBase + m0 + i;
        if (row >= N) continue;
        float dinv = rsqrtf((float)g_deg[row] + 1.0f);
        size_t base = (size_t)row * (D / 4) + (n0 >> 2);
        float4 v0, v1;
        v0.x = c[i][0] * dinv; v0.y = c[i][1] * dinv;
        v0.z = c[i][2] * dinv; v0.w = c[i][3] * dinv;
        v1.x = c[i][4] * dinv; v1.y = c[i][5] * dinv;
        v1.z = c[i][6] * dinv; v1.w = c[i][7] * dinv;
        g_g4[base]       = v0;
        g_g4[base + 1]   = v1;
        g_agg4[base]     = v0;
        g_agg4[base + 1] = v1;
    }
}

// Edge scatter: one warp per edge; lane l handles float4 #l of the row.
__global__ __launch_bounds__(256) void edge_kernel(
    const void* __restrict__ ei, int E)
{
    int w = (blockIdx.x * blockDim.x + threadIdx.x) >> 5;
    int lane = threadIdx.x & 31;
    if (w >= E) return;

    int s, d;
    if (g_is64) {
        const long long* p = (const long long*)ei;
        s = (int)p[w];
        d = (int)p[(size_t)E + w];
    } else {
        const int* p = (const int*)ei;
        s = p[w];
        d = p[(size_t)E + w];
    }
    if ((unsigned)s >= (unsigned)N_NODES || (unsigned)d >= (unsigned)N_NODES) return;

    float4 v = g_g4[(size_t)s * (D / 4) + lane];
    float4* p4 = &g_agg4[(size_t)d * (D / 4) + lane];
    asm volatile("red.global.add.v4.f32 [%0], {%1,%2,%3,%4};"
                 :: "l"(p4), "f"(v.x), "f"(v.y), "f"(v.z), "f"(v.w)
                 : "memory");
}

// out = relu(dinv * agg + b)
__global__ __launch_bounds__(256) void final_kernel(
    const float* __restrict__ b, float* __restrict__ out, int N)
{
    int idx = blockIdx.x * blockDim.x + threadIdx.x;   // over N*32 float4s
    if (idx >= N * (D / 4)) return;
    int row = idx >> 5;
    int c4 = idx & 31;
    float dinv = rsqrtf((float)g_deg[row] + 1.0f);
    float4 v = g_agg4[idx];
    float4 bb = *(const float4*)(b + c4 * 4);
    float4 o;
    o.x = fmaxf(fmaf(v.x, dinv, bb.x), 0.0f);
    o.y = fmaxf(fmaf(v.y, dinv, bb.y), 0.0f);
    o.z = fmaxf(fmaf(v.z, dinv, bb.z), 0.0f);
    o.w = fmaxf(fmaf(v.w, dinv, bb.w), 0.0f);
    *(float4*)(out + (size_t)idx * 4) = o;
}

// ---------------- launch ----------------
extern "C" void kernel_launch(void* const* d_in, const int* in_sizes, int n_in,
                              void* d_out, int out_size)
{
    const float* x  = (const float*)d_in[0];
    const void*  ei = d_in[1];                 // [2, E], int64 OR int32 (detected)
    const float* W  = (const float*)d_in[2];
    const float* b  = (const float*)d_in[3];
    float* out = (float*)d_out;

    const int N = in_sizes[0] / D;
    const int E = in_sizes[1] / 2;

    // 0. detect index dtype (int64 vs int32)
    detect_kernel<<<1, 256>>>((const int*)ei, 2048);
    // 1. zero degrees
    init_deg_kernel<<<(N + 255) / 256, 256>>>(N);
    // 2. count degrees from dst row
    deg_kernel<<<(E + 255) / 256, 256>>>(ei, E);
    // 3. transpose W
    transpose_W_kernel<<<(D * D + 255) / 256, 256>>>(W);
    // 4. h = x @ W^T, scaled by dinv -> g, agg
    gemm_scale_kernel<<<(N + BM - 1) / BM, 256>>>(x, N);
    // 5. scatter-add over edges (1 warp per edge)
    edge_kernel<<<(E * 32 + 255) / 256, 256>>>(ei, E);
    // 6. epilogue
    final_kernel<<<(N * (D / 4) + 255) / 256, 256>>>(b, out, N);
}

// round 7
// speedup vs baseline: 1.7545x; 1.7545x over previous
#include <cuda_runtime.h>
#include <cstdint>

#define N_NODES 100000
#define MAX_EDGES 1700000
#define D 128
#define SCAN_BLK 1024

// ---------------- scratch ----------------
__device__ float4 g_g4[(size_t)N_NODES * (D / 4)];   // g = dinv * (x @ W^T)
__device__ float  g_Wt[D * D];                       // W transposed
__device__ int    g_deg[N_NODES];                    // in-degree per dst (edges only)
__device__ int    g_off[N_NODES];                    // CSR exclusive offsets
__device__ int    g_cur[N_NODES];                    // scatter cursors
__device__ int    g_csr[MAX_EDGES];                  // src index per CSR slot
__device__ int    g_bsum[128];                       // per-block scan sums
__device__ int    g_boff[128];                       // per-block scan offsets
__device__ int    g_is64;                            // edge_index dtype flag

// ---------------- dtype detect ----------------
__global__ void detect_kernel(const int* __restrict__ ei32, int n_pairs) {
    __shared__ int nz;
    if (threadIdx.x == 0) nz = 0;
    __syncthreads();
    int local = 0;
    for (int i = threadIdx.x; i < n_pairs; i += blockDim.x)
        if (ei32[2 * i + 1] != 0) local = 1;
    if (local) atomicOr(&nz, 1);
    __syncthreads();
    if (threadIdx.x == 0) g_is64 = (nz == 0) ? 1 : 0;
}

__global__ void init_deg_kernel(int n) {
    int i = blockIdx.x * blockDim.x + threadIdx.x;
    if (i < n) g_deg[i] = 0;
}

__global__ void deg_kernel(const void* __restrict__ ei, int E) {
    int i = blockIdx.x * blockDim.x + threadIdx.x;
    if (i >= E) return;
    int d;
    if (g_is64) d = (int)((const long long*)ei)[(size_t)E + i];
    else        d = ((const int*)ei)[(size_t)E + i];
    if ((unsigned)d < (unsigned)N_NODES) atomicAdd(&g_deg[d], 1);
}

// ---------------- exclusive scan of g_deg -> g_off (3 kernels) ----------------
__global__ void scan1_kernel(int n) {
    __shared__ int sh[SCAN_BLK];
    int t = threadIdx.x;
    int i = blockIdx.x * SCAN_BLK + t;
    int v = (i < n) ? g_deg[i] : 0;
    sh[t] = v;
    __syncthreads();
#pragma unroll
    for (int o = 1; o < SCAN_BLK; o <<= 1) {
        int add = (t >= o) ? sh[t - o] : 0;
        __syncthreads();
        sh[t] += add;
        __syncthreads();
    }
    if (i < n) g_off[i] = sh[t] - v;          // exclusive
    if (t == SCAN_BLK - 1) g_bsum[blockIdx.x] = sh[t];
}

__global__ void scan2_kernel(int nb) {
    if (threadIdx.x == 0) {
        int run = 0;
        for (int j = 0; j < nb; j++) { g_boff[j] = run; run += g_bsum[j]; }
    }
}

__global__ void scan3_kernel(int n) {
    int i = blockIdx.x * SCAN_BLK + threadIdx.x;
    if (i < n) {
        int o = g_off[i] + g_boff[blockIdx.x];
        g_off[i] = o;
        g_cur[i] = o;
    }
}

// ---------------- scatter edges into CSR (by dst) ----------------
__global__ void csr_kernel(const void* __restrict__ ei, int E) {
    int i = blockIdx.x * blockDim.x + threadIdx.x;
    if (i >= E) return;
    int s, d;
    if (g_is64) {
        const long long* p = (const long long*)ei;
        s = (int)p[i];
        d = (int)p[(size_t)E + i];
    } else {
        const int* p = (const int*)ei;
        s = p[i];
        d = p[(size_t)E + i];
    }
    if ((unsigned)s >= (unsigned)N_NODES || (unsigned)d >= (unsigned)N_NODES) return;
    int pos = atomicAdd(&g_cur[d], 1);
    g_csr[pos] = s;
}

__global__ void transpose_W_kernel(const float* __restrict__ W) {
    int i = blockIdx.x * blockDim.x + threadIdx.x;
    if (i < D * D) {
        int n = i >> 7;
        int k = i & 127;
        g_Wt[k * D + n] = W[n * D + k];
    }
}

// ---------------- SGEMM: g = dinv * (x @ W^T) ----------------
#define BM 128
#define KT 32
__global__ __launch_bounds__(256) void gemm_scale_kernel(
    const float* __restrict__ x, int N)
{
    __shared__ float xs[BM][KT + 1];
    __shared__ float ws[KT][D];

    const int tid = threadIdx.x;
    const int tx = tid & 15;
    const int ty = tid >> 4;
    const int m0 = ty * 8;
    const int n0 = tx * 8;
    const int rowBase = blockIdx.x * BM;

    float c[8][8];
#pragma unroll
    for (int i = 0; i < 8; i++)
#pragma unroll
        for (int j = 0; j < 8; j++) c[i][j] = 0.0f;

    for (int kt = 0; kt < D; kt += KT) {
#pragma unroll
        for (int it = 0; it < 4; it++) {
            int i = tid + it * 256;
            int m = i >> 3;
            int kq = i & 7;
            float4 v = make_float4(0.f, 0.f, 0.f, 0.f);
            int row = rowBase + m;
            if (row < N)
                v = *(const float4*)(x + (size_t)row * D + kt + kq * 4);
            xs[m][kq * 4 + 0] = v.x;
            xs[m][kq * 4 + 1] = v.y;
            xs[m][kq * 4 + 2] = v.z;
            xs[m][kq * 4 + 3] = v.w;
        }
#pragma unroll
        for (int it = 0; it < 4; it++) {
            int i = tid + it * 256;
            int k = i >> 5;
            int nq = i & 31;
            float4 v = *(const float4*)(g_Wt + (size_t)(kt + k) * D + nq * 4);
            ws[k][nq * 4 + 0] = v.x;
            ws[k][nq * 4 + 1] = v.y;
            ws[k][nq * 4 + 2] = v.z;
            ws[k][nq * 4 + 3] = v.w;
        }
        __syncthreads();

#pragma unroll 8
        for (int k = 0; k < KT; k++) {
            float a[8], b[8];
#pragma unroll
            for (int i = 0; i < 8; i++) a[i] = xs[m0 + i][k];
#pragma unroll
            for (int j = 0; j < 8; j++) b[j] = ws[k][n0 + j];
#pragma unroll
            for (int i = 0; i < 8; i++)
#pragma unroll
                for (int j = 0; j < 8; j++)
                    c[i][j] = fmaf(a[i], b[j], c[i][j]);
        }
        __syncthreads();
    }

#pragma unroll
    for (int i = 0; i < 8; i++) {
        int row = rowBase + m0 + i;
        if (row >= N) continue;
        float dinv = rsqrtf((float)g_deg[row] + 1.0f);
        size_t base = (size_t)row * (D / 4) + (n0 >> 2);
        float4 v0, v1;
        v0.x = c[i][0] * dinv; v0.y = c[i][1] * dinv;
        v0.z = c[i][2] * dinv; v0.w = c[i][3] * dinv;
        v1.x = c[i][4] * dinv; v1.y = c[i][5] * dinv;
        v1.z = c[i][6] * dinv; v1.w = c[i][7] * dinv;
        g_g4[base]     = v0;
        g_g4[base + 1] = v1;
    }
}

// ---------------- aggregate + epilogue: warp per node ----------------
// out[n] = relu( dinv[n] * ( g[n] + sum_{e in CSR[n]} g[src_e] ) + b )
__global__ __launch_bounds__(256) void agg_kernel(
    const float* __restrict__ b, float* __restrict__ out, int N)
{
    int w = (blockIdx.x * blockDim.x + threadIdx.x) >> 5;
    int lane = threadIdx.x & 31;
    if (w >= N) return;

    int deg = g_deg[w];
    int e = g_off[w];
    float dinv = rsqrtf((float)deg + 1.0f);

    float4 acc = g_g4[(size_t)w * 32 + lane];   // self loop

    int cnt = deg;
    while (cnt >= 4) {
        int s0 = __ldg(&g_csr[e + 0]);
        int s1 = __ldg(&g_csr[e + 1]);
        int s2 = __ldg(&g_csr[e + 2]);
        int s3 = __ldg(&g_csr[e + 3]);
        float4 v0 = g_g4[(size_t)s0 * 32 + lane];
        float4 v1 = g_g4[(size_t)s1 * 32 + lane];
        float4 v2 = g_g4[(size_t)s2 * 32 + lane];
        float4 v3 = g_g4[(size_t)s3 * 32 + lane];
        acc.x += (v0.x + v1.x) + (v2.x + v3.x);
        acc.y += (v0.y + v1.y) + (v2.y + v3.y);
        acc.z += (v0.z + v1.z) + (v2.z + v3.z);
        acc.w += (v0.w + v1.w) + (v2.w + v3.w);
        e += 4; cnt -= 4;
    }
    while (cnt > 0) {
        int s = __ldg(&g_csr[e]);
        float4 v = g_g4[(size_t)s * 32 + lane];
        acc.x += v.x; acc.y += v.y; acc.z += v.z; acc.w += v.w;
        e++; cnt--;
    }

    float4 bb = *(const float4*)(b + lane * 4);
    float4 o;
    o.x = fmaxf(fmaf(acc.x, dinv, bb.x), 0.0f);
    o.y = fmaxf(fmaf(acc.y, dinv, bb.y), 0.0f);
    o.z = fmaxf(fmaf(acc.z, dinv, bb.z), 0.0f);
    o.w = fmaxf(fmaf(acc.w, dinv, bb.w), 0.0f);
    *(float4*)(out + (size_t)w * D + lane * 4) = o;
}

// ---------------- launch ----------------
extern "C" void kernel_launch(void* const* d_in, const int* in_sizes, int n_in,
                              void* d_out, int out_size)
{
    const float* x  = (const float*)d_in[0];
    const void*  ei = d_in[1];                 // [2, E], int64 OR int32 (detected)
    const float* W  = (const float*)d_in[2];
    const float* b  = (const float*)d_in[3];
    float* out = (float*)d_out;

    const int N = in_sizes[0] / D;
    const int E = in_sizes[1] / 2;
    const int NB = (N + SCAN_BLK - 1) / SCAN_BLK;

    detect_kernel<<<1, 256>>>((const int*)ei, 2048);
    init_deg_kernel<<<(N + 255) / 256, 256>>>(N);
    deg_kernel<<<(E + 255) / 256, 256>>>(ei, E);
    // exclusive scan deg -> off, cursors
    scan1_kernel<<<NB, SCAN_BLK>>>(N);
    scan2_kernel<<<1, 32>>>(NB);
    scan3_kernel<<<NB, SCAN_BLK>>>(N);
    // CSR scatter
    csr_kernel<<<(E + 255) / 256, 256>>>(ei, E);
    // weights + GEMM (overlappable work ordering: transpose before gemm)
    transpose_W_kernel<<<(D * D + 255) / 256, 256>>>(W);
    gemm_scale_kernel<<<(N + BM - 1) / BM, 256>>>(x, N);
    // fused gather-aggregate + bias + relu
    agg_kernel<<<(N * 32 + 255) / 256, 256>>>(b, out, N);
}

// round 8
// speedup vs baseline: 1.8144x; 1.0341x over previous
#include <cuda_runtime.h>
#include <cstdint>

#define N_NODES 100000
#define MAX_EDGES 1700000
#define D 128
#define SCAN_BLK 1024

// ---------------- scratch ----------------
__device__ float4 g_g4[(size_t)N_NODES * (D / 4)];   // g = dinv * (x @ W^T)
__device__ float  g_Wt[D * D];                       // W transposed
__device__ int    g_deg[N_NODES];                    // in-degree per dst (edges only)
__device__ int    g_off[N_NODES];                    // CSR exclusive offsets
__device__ int    g_cur[N_NODES];                    // scatter cursors
__device__ int    g_csr[MAX_EDGES];                  // src index per CSR slot
__device__ int    g_bsum[128];                       // per-block scan sums
__device__ int    g_boff[128];                       // per-block scan offsets
__device__ int    g_is64;                            // edge_index dtype flag

// ---------------- detect dtype + zero degrees (fused) ----------------
// int64 indices < 2^31 viewed as int32 are [lo,0,lo,0,...]; int32 has random
// nonzero odd words. Block 0 additionally decides the flag.
__global__ void detect_init_kernel(const int* __restrict__ ei32, int n_pairs, int n) {
    int i = blockIdx.x * blockDim.x + threadIdx.x;
    if (i < n) g_deg[i] = 0;

    if (blockIdx.x == 0) {
        __shared__ int nz;
        if (threadIdx.x == 0) nz = 0;
        __syncthreads();
        int local = 0;
        for (int j = threadIdx.x; j < n_pairs; j += blockDim.x)
            if (ei32[2 * j + 1] != 0) local = 1;
        if (local) atomicOr(&nz, 1);
        __syncthreads();
        if (threadIdx.x == 0) g_is64 = (nz == 0) ? 1 : 0;
    }
}

__global__ void deg_kernel(const void* __restrict__ ei, int E) {
    int i = blockIdx.x * blockDim.x + threadIdx.x;
    if (i >= E) return;
    int d;
    if (g_is64) d = (int)((const long long*)ei)[(size_t)E + i];
    else        d = ((const int*)ei)[(size_t)E + i];
    if ((unsigned)d < (unsigned)N_NODES) atomicAdd(&g_deg[d], 1);
}

// ---------------- exclusive scan of g_deg -> g_off (3 kernels) ----------------
__global__ void scan1_kernel(int n) {
    __shared__ int sh[SCAN_BLK];
    int t = threadIdx.x;
    int i = blockIdx.x * SCAN_BLK + t;
    int v = (i < n) ? g_deg[i] : 0;
    sh[t] = v;
    __syncthreads();
#pragma unroll
    for (int o = 1; o < SCAN_BLK; o <<= 1) {
        int add = (t >= o) ? sh[t - o] : 0;
        __syncthreads();
        sh[t] += add;
        __syncthreads();
    }
    if (i < n) g_off[i] = sh[t] - v;          // exclusive
    if (t == SCAN_BLK - 1) g_bsum[blockIdx.x] = sh[t];
}

// Parallel scan of per-block sums (replaces the serial 1-thread loop).
__global__ void scan2_kernel(int nb) {
    __shared__ int sh[128];
    int t = threadIdx.x;
    int v = (t < nb) ? g_bsum[t] : 0;
    sh[t] = v;
    __syncthreads();
#pragma unroll
    for (int o = 1; o < 128; o <<= 1) {
        int add = (t >= o) ? sh[t - o] : 0;
        __syncthreads();
        sh[t] += add;
        __syncthreads();
    }
    if (t < nb) g_boff[t] = sh[t] - v;        // exclusive
}

__global__ void scan3_kernel(int n) {
    int i = blockIdx.x * SCAN_BLK + threadIdx.x;
    if (i < n) {
        int o = g_off[i] + g_boff[blockIdx.x];
        g_off[i] = o;
        g_cur[i] = o;
    }
}

// ---------------- scatter edges into CSR (by dst) ----------------
__global__ void csr_kernel(const void* __restrict__ ei, int E) {
    int i = blockIdx.x * blockDim.x + threadIdx.x;
    if (i >= E) return;
    int s, d;
    if (g_is64) {
        const long long* p = (const long long*)ei;
        s = (int)p[i];
        d = (int)p[(size_t)E + i];
    } else {
        const int* p = (const int*)ei;
        s = p[i];
        d = p[(size_t)E + i];
    }
    if ((unsigned)s >= (unsigned)N_NODES || (unsigned)d >= (unsigned)N_NODES) return;
    int pos = atomicAdd(&g_cur[d], 1);
    g_csr[pos] = s;
}

__global__ void transpose_W_kernel(const float* __restrict__ W) {
    int i = blockIdx.x * blockDim.x + threadIdx.x;
    if (i < D * D) {
        int n = i >> 7;
        int k = i & 127;
        g_Wt[k * D + n] = W[n * D + k];
    }
}

// ---------------- SGEMM: g = dinv * (x @ W^T) ----------------
// k-major smem, 16B-aligned pads, vectorized LDS.128 inner loop.
#define BM 128
#define KT 32
#define XPAD 4
#define WPAD 4
__global__ __launch_bounds__(256) void gemm_scale_kernel(
    const float* __restrict__ x, int N)
{
    __shared__ float xs[KT][BM + XPAD];   // [k][m], row stride 132 (528B, 16B mult)
    __shared__ float ws[KT][D + WPAD];    // [k][n], row stride 132

    const int tid = threadIdx.x;
    const int tx = tid & 15;
    const int ty = tid >> 4;
    const int m0 = ty * 8;
    const int n0 = tx * 8;
    const int rowBase = blockIdx.x * BM;

    float c[8][8];
#pragma unroll
    for (int i = 0; i < 8; i++)
#pragma unroll
        for (int j = 0; j < 8; j++) c[i][j] = 0.0f;

    for (int kt = 0; kt < D; kt += KT) {
        // x tile: 128 rows x 32 k, read float4 along k, store transposed
#pragma unroll
        for (int it = 0; it < 4; it++) {
            int i = tid + it * 256;            // 0..1023 float4s
            int m = i >> 3;
            int kq = i & 7;
            float4 v = make_float4(0.f, 0.f, 0.f, 0.f);
            int row = rowBase + m;
            if (row < N)
                v = *(const float4*)(x + (size_t)row * D + kt + kq * 4);
            xs[kq * 4 + 0][m] = v.x;
            xs[kq * 4 + 1][m] = v.y;
            xs[kq * 4 + 2][m] = v.z;
            xs[kq * 4 + 3][m] = v.w;
        }
        // W tile: 32 k x 128 n, coalesced float4 from Wt, float4 store
#pragma unroll
        for (int it = 0; it < 4; it++) {
            int i = tid + it * 256;
            int k = i >> 5;
            int nq = i & 31;
            float4 v = *(const float4*)(g_Wt + (size_t)(kt + k) * D + nq * 4);
            *(float4*)&ws[k][nq * 4] = v;
        }
        __syncthreads();

#pragma unroll
        for (int k = 0; k < KT; k++) {
            float4 a0 = *(const float4*)&xs[k][m0];
            float4 a1 = *(const float4*)&xs[k][m0 + 4];
            float4 b0 = *(const float4*)&ws[k][n0];
            float4 b1 = *(const float4*)&ws[k][n0 + 4];
            float a[8] = {a0.x, a0.y, a0.z, a0.w, a1.x, a1.y, a1.z, a1.w};
            float b[8] = {b0.x, b0.y, b0.z, b0.w, b1.x, b1.y, b1.z, b1.w};
#pragma unroll
            for (int i = 0; i < 8; i++)
#pragma unroll
                for (int j = 0; j < 8; j++)
                    c[i][j] = fmaf(a[i], b[j], c[i][j]);
        }
        __syncthreads();
    }

#pragma unroll
    for (int i = 0; i < 8; i++) {
        int row = rowBase + m0 + i;
        if (row >= N) continue;
        float dinv = rsqrtf((float)g_deg[row] + 1.0f);
        size_t base = (size_t)row * (D / 4) + (n0 >> 2);
        float4 v0, v1;
        v0.x = c[i][0] * dinv; v0.y = c[i][1] * dinv;
        v0.z = c[i][2] * dinv; v0.w = c[i][3] * dinv;
        v1.x = c[i][4] * dinv; v1.y = c[i][5] * dinv;
        v1.z = c[i][6] * dinv; v1.w = c[i][7] * dinv;
        g_g4[base]     = v0;
        g_g4[base + 1] = v1;
    }
}

// ---------------- aggregate + epilogue: warp per node, MLP=8 ----------------
__global__ __launch_bounds__(256) void agg_kernel(
    const float* __restrict__ b, float* __restrict__ out, int N)
{
    int w = (blockIdx.x * blockDim.x + threadIdx.x) >> 5;
    int lane = threadIdx.x & 31;
    if (w >= N) return;

    int deg = g_deg[w];
    int e = g_off[w];
    float dinv = rsqrtf((float)deg + 1.0f);

    float4 acc = g_g4[(size_t)w * 32 + lane];   // self loop

    int cnt = deg;
    while (cnt >= 8) {
        int s[8];
#pragma unroll
        for (int u = 0; u < 8; u++) s[u] = __ldg(&g_csr[e + u]);
        float4 v[8];
#pragma unroll
        for (int u = 0; u < 8; u++) v[u] = g_g4[(size_t)s[u] * 32 + lane];
        float x0 = (v[0].x + v[1].x) + (v[2].x + v[3].x);
        float x1 = (v[4].x + v[5].x) + (v[6].x + v[7].x);
        float y0 = (v[0].y + v[1].y) + (v[2].y + v[3].y);
        float y1 = (v[4].y + v[5].y) + (v[6].y + v[7].y);
        float z0 = (v[0].z + v[1].z) + (v[2].z + v[3].z);
        float z1 = (v[4].z + v[5].z) + (v[6].z + v[7].z);
        float w0 = (v[0].w + v[1].w) + (v[2].w + v[3].w);
        float w1 = (v[4].w + v[5].w) + (v[6].w + v[7].w);
        acc.x += x0 + x1; acc.y += y0 + y1;
        acc.z += z0 + z1; acc.w += w0 + w1;
        e += 8; cnt -= 8;
    }
    if (cnt >= 4) {
        int s0 = __ldg(&g_csr[e + 0]);
        int s1 = __ldg(&g_csr[e + 1]);
        int s2 = __ldg(&g_csr[e + 2]);
        int s3 = __ldg(&g_csr[e + 3]);
        float4 v0 = g_g4[(size_t)s0 * 32 + lane];
        float4 v1 = g_g4[(size_t)s1 * 32 + lane];
        float4 v2 = g_g4[(size_t)s2 * 32 + lane];
        float4 v3 = g_g4[(size_t)s3 * 32 + lane];
        acc.x += (v0.x + v1.x) + (v2.x + v3.x);
        acc.y += (v0.y + v1.y) + (v2.y + v3.y);
        acc.z += (v0.z + v1.z) + (v2.z + v3.z);
        acc.w += (v0.w + v1.w) + (v2.w + v3.w);
        e += 4; cnt -= 4;
    }
    while (cnt > 0) {
        int s = __ldg(&g_csr[e]);
        float4 v = g_g4[(size_t)s * 32 + lane];
        acc.x += v.x; acc.y += v.y; acc.z += v.z; acc.w += v.w;
        e++; cnt--;
    }

    float4 bb = *(const float4*)(b + lane * 4);
    float4 o;
    o.x = fmaxf(fmaf(acc.x, dinv, bb.x), 0.0f);
    o.y = fmaxf(fmaf(acc.y, dinv, bb.y), 0.0f);
    o.z = fmaxf(fmaf(acc.z, dinv, bb.z), 0.0f);
    o.w = fmaxf(fmaf(acc.w, dinv, bb.w), 0.0f);
    *(float4*)(out + (size_t)w * D + lane * 4) = o;
}

// ---------------- launch ----------------
extern "C" void kernel_launch(void* const* d_in, const int* in_sizes, int n_in,
                              void* d_out, int out_size)
{
    const float* x  = (const float*)d_in[0];
    const void*  ei = d_in[1];                 // [2, E], int64 OR int32 (detected)
    const float* W  = (const float*)d_in[2];
    const float* b  = (const float*)d_in[3];
    float* out = (float*)d_out;

    const int N = in_sizes[0] / D;
    const int E = in_sizes[1] / 2;
    const int NB = (N + SCAN_BLK - 1) / SCAN_BLK;

    detect_init_kernel<<<(N + 255) / 256, 256>>>((const int*)ei, 2048, N);
    deg_kernel<<<(E + 255) / 256, 256>>>(ei, E);
    scan1_kernel<<<NB, SCAN_BLK>>>(N);
    scan2_kernel<<<1, 128>>>(NB);
    scan3_kernel<<<NB, SCAN_BLK>>>(N);
    csr_kernel<<<(E + 255) / 256, 256>>>(ei, E);
    transpose_W_kernel<<<(D * D + 255) / 256, 256>>>(W);
    gemm_scale_kernel<<<(N + BM - 1) / BM, 256>>>(x, N);
    agg_kernel<<<(N * 32 + 255) / 256, 256>>>(b, out, N);
}